// round 6
// baseline (speedup 1.0000x reference)
#include <cuda_runtime.h>
#include <cstdint>
#include <math.h>
#include <float.h>

#define BB 2
#define CC 512
#define LQ 2048
#define LC 4096
#define HH 8
#define DH 64
#define BHD 16
#define TK 512

// ---------------- scratch ----------------
__device__ float g_ctxn[BB*CC*LC];
__device__ float g_qsn [BB*CC*LQ];
__device__ float g_kv  [BB*2*CC*LC];
__device__ float g_qprj[BB*CC*LQ];
__device__ float g_K   [BHD*LC*DH];
__device__ float g_V   [BHD*LC*DH];
__device__ float g_Qn  [BHD*LQ*DH];
__device__ float g_Qs  [BHD*TK*DH];
__device__ float g_mind[BHD*LC];
__device__ int   g_idx [BHD*TK];
__device__ float g_Ksel[BHD*TK*DH];
__device__ float g_Vsel[BHD*TK*DH];
__device__ float g_aout[BB*CC*LQ];
__device__ float g_oprj[BB*CC*LQ];

// ---------------- channel LayerNorm over C for each (b,l) ----------------
__global__ void ln_kernel(const float* __restrict__ x, const float* __restrict__ g,
                          const float* __restrict__ bta, float* __restrict__ y,
                          int C, int L) {
    int l = blockIdx.x * blockDim.x + threadIdx.x;
    int b = blockIdx.y;
    if (l >= L) return;
    const float* xp = x + (size_t)b * C * L + l;
    float s = 0.f, s2 = 0.f;
    for (int c = 0; c < C; c++) { float v = xp[(size_t)c * L]; s += v; s2 += v * v; }
    float mean = s / C;
    float var = s2 / C - mean * mean;
    float inv = rsqrtf(var + 1e-5f);
    float* yp = y + (size_t)b * C * L + l;
    for (int c = 0; c < C; c++) {
        float v = xp[(size_t)c * L];
        yp[(size_t)c * L] = (v - mean) * inv * g[c] + bta[c];
    }
}

__global__ void ln_resid_kernel(const float* __restrict__ x, const float* __restrict__ g,
                                const float* __restrict__ bta, const float* __restrict__ qsrc,
                                const float* __restrict__ gamma, float* __restrict__ y,
                                int C, int L) {
    int l = blockIdx.x * blockDim.x + threadIdx.x;
    int b = blockIdx.y;
    if (l >= L) return;
    const float* xp = x + (size_t)b * C * L + l;
    float s = 0.f, s2 = 0.f;
    for (int c = 0; c < C; c++) { float v = xp[(size_t)c * L]; s += v; s2 += v * v; }
    float mean = s / C;
    float var = s2 / C - mean * mean;
    float inv = rsqrtf(var + 1e-5f);
    float gm = gamma[0];
    const float* qp = qsrc + (size_t)b * C * L + l;
    float* yp = y + (size_t)b * C * L + l;
    for (int c = 0; c < C; c++) {
        float v = xp[(size_t)c * L];
        yp[(size_t)c * L] = gm * ((v - mean) * inv * g[c] + bta[c]) + qp[(size_t)c * L];
    }
}

// ---------------- 128x128x8 fp32 SGEMM: C[b] = A(MxK) * X[b](KxN) ------------
__global__ __launch_bounds__(256) void sgemm128(const float* __restrict__ A,
                                                const float* __restrict__ X,
                                                float* __restrict__ C,
                                                int K, int N, size_t x_bstride, size_t c_bstride) {
    int bz = blockIdx.z;
    const float* Xb = X + (size_t)bz * x_bstride;
    float* Cb = C + (size_t)bz * c_bstride;
    int bm = blockIdx.y, bn = blockIdx.x;
    __shared__ float As[8][128];
    __shared__ float Bs[8][128];
    int tid = threadIdx.x;
    float acc[8][8];
#pragma unroll
    for (int i = 0; i < 8; i++)
#pragma unroll
        for (int j = 0; j < 8; j++) acc[i][j] = 0.f;

    int a_row = tid >> 1, a_col = (tid & 1) * 4;
    int b_row = tid >> 5, b_col = (tid & 31) * 4;
    const float* Ap = A + (size_t)(bm * 128 + a_row) * K + a_col;
    const float* Xp = Xb + (size_t)b_row * N + bn * 128 + b_col;
    int ty = tid >> 4, tx = tid & 15;

    for (int k0 = 0; k0 < K; k0 += 8) {
        float4 av = *(const float4*)(Ap + k0);
        As[a_col + 0][a_row] = av.x;
        As[a_col + 1][a_row] = av.y;
        As[a_col + 2][a_row] = av.z;
        As[a_col + 3][a_row] = av.w;
        *(float4*)&Bs[b_row][b_col] = *(const float4*)(Xp + (size_t)k0 * N);
        __syncthreads();
#pragma unroll
        for (int k = 0; k < 8; k++) {
            float4 a0 = *(const float4*)&As[k][ty * 4];
            float4 a1 = *(const float4*)&As[k][64 + ty * 4];
            float4 b0 = *(const float4*)&Bs[k][tx * 4];
            float4 b1 = *(const float4*)&Bs[k][64 + tx * 4];
            float ra[8] = {a0.x, a0.y, a0.z, a0.w, a1.x, a1.y, a1.z, a1.w};
            float rb[8] = {b0.x, b0.y, b0.z, b0.w, b1.x, b1.y, b1.z, b1.w};
#pragma unroll
            for (int i = 0; i < 8; i++)
#pragma unroll
                for (int j = 0; j < 8; j++) acc[i][j] += ra[i] * rb[j];
        }
        __syncthreads();
    }
#pragma unroll
    for (int i = 0; i < 8; i++) {
        int m = bm * 128 + ((i < 4) ? (ty * 4 + i) : (64 + ty * 4 + (i - 4)));
        float4 c0 = {acc[i][0], acc[i][1], acc[i][2], acc[i][3]};
        float4 c1 = {acc[i][4], acc[i][5], acc[i][6], acc[i][7]};
        *(float4*)&Cb[(size_t)m * N + bn * 128 + tx * 4]      = c0;
        *(float4*)&Cb[(size_t)m * N + bn * 128 + 64 + tx * 4] = c1;
    }
}

// ------------- head fold + optional L2-norm + transpose to (bh, L, 64) -------
__global__ void nt_kernel(const float* __restrict__ src, float* __restrict__ dst,
                          int L, int chan_total, int chan0, int do_norm) {
    __shared__ float s[64][33];
    __shared__ float inv[32];
    int b = blockIdx.z, h = blockIdx.y, lt = blockIdx.x;
    int tid = threadIdx.x;
    const float* sp = src + ((size_t)b * chan_total + chan0 + h * 64) * L + (size_t)lt * 32;
    int lcol = tid & 31, drow0 = tid >> 5;
#pragma unroll
    for (int j = 0; j < 8; j++) {
        int d = drow0 + j * 8;
        s[d][lcol] = sp[(size_t)d * L + lcol];
    }
    __syncthreads();
    if (tid < 32) {
        float s2 = 0.f;
#pragma unroll
        for (int d = 0; d < 64; d++) { float v = s[d][tid]; s2 += v * v; }
        inv[tid] = 1.0f / fmaxf(sqrtf(s2), 1e-12f);
    }
    __syncthreads();
    float* dp = dst + ((size_t)(b * HH + h) * L + (size_t)lt * 32) * 64;
#pragma unroll
    for (int j = 0; j < 8; j++) {
        int flat = j * 256 + tid;
        int l = flat >> 6, d = flat & 63;
        float v = s[d][l];
        dp[(size_t)l * 64 + d] = do_norm ? v * inv[l] : v;
    }
}

// ---------------- threefry-2x32 (JAX) ----------------
__device__ __forceinline__ uint32_t rotl32(uint32_t x, int r) { return (x << r) | (x >> (32 - r)); }
__device__ __forceinline__ void threefry2x32(uint32_t k0, uint32_t k1, uint32_t c0, uint32_t c1,
                                             uint32_t& o0, uint32_t& o1) {
    uint32_t ks2 = k0 ^ k1 ^ 0x1BD11BDAu;
    uint32_t x0 = c0 + k0, x1 = c1 + k1;
#define TFR(r) { x0 += x1; x1 = rotl32(x1, (r)); x1 ^= x0; }
    TFR(13) TFR(15) TFR(26) TFR(6)   x0 += k1;  x1 += ks2 + 1u;
    TFR(17) TFR(29) TFR(16) TFR(24)  x0 += ks2; x1 += k0 + 2u;
    TFR(13) TFR(15) TFR(26) TFR(6)   x0 += k0;  x1 += k1 + 3u;
    TFR(17) TFR(29) TFR(16) TFR(24)  x0 += k1;  x1 += ks2 + 4u;
    TFR(13) TFR(15) TFR(26) TFR(6)   x0 += ks2; x1 += k0 + 5u;
#undef TFR
    o0 = x0; o1 = x1;
}

// JAX randint(key(42), (16,512), 0, 2048), partitionable threefry (modern default):
//   _randint: k1,k2 = split(key); lower_bits = random_bits(k2, 32, shape)  [8192 draws]
//   split (fold-like): child_i = threefry(key, hi=0, lo=i), BOTH words -> k2 = TF((0,42),0,1)
//   random_bits (partitionable, 32-bit): counter = 64-bit iota j -> (hi=0, lo=j),
//     bits[j] = o0 ^ o1
//   multiplier = (2^16 % 2048)^2 % 2048 = 0  ->  idx[j] = bits[j] & 2047
__global__ void qsmall_kernel(const float* __restrict__ Qn, float* __restrict__ Qs) {
    __shared__ int sidx;
    int bh = blockIdx.y, t = blockIdx.x;
    if (threadIdx.x == 0) {
        uint32_t k2x, k2y, o0, o1;
        threefry2x32(0u, 42u, 0u, 1u, k2x, k2y);      // k2 = split(key(42))[1]
        uint32_t j = (uint32_t)(bh * TK + t);         // flat counter, no offset
        threefry2x32(k2x, k2y, 0u, j, o0, o1);
        sidx = (int)((o0 ^ o1) & 2047u);
    }
    __syncthreads();
    int d = threadIdx.x;
    Qs[((size_t)bh * TK + t) * DH + d] = Qn[((size_t)bh * LQ + sidx) * DH + d];
}

// ---------------- min-L1 distance: one key per thread ----------------
__global__ __launch_bounds__(256) void dist_kernel(const float* __restrict__ Kn,
                                                   const float* __restrict__ Qs,
                                                   float* __restrict__ mind) {
    __shared__ __align__(16) float sq[64][64];
    int bh = blockIdx.y;
    int key = blockIdx.x * 256 + threadIdx.x;
    float kreg[64];
    const float4* kp = (const float4*)(Kn + ((size_t)bh * LC + key) * DH);
#pragma unroll
    for (int i = 0; i < 16; i++) {
        float4 v = kp[i];
        kreg[i*4+0] = v.x; kreg[i*4+1] = v.y; kreg[i*4+2] = v.z; kreg[i*4+3] = v.w;
    }
    float best = FLT_MAX;
    for (int q0 = 0; q0 < TK; q0 += 64) {
        __syncthreads();
        const float4* qp = (const float4*)(Qs + ((size_t)bh * TK + q0) * DH);
        for (int t = threadIdx.x; t < 64 * 16; t += 256)
            ((float4*)&sq[0][0])[t] = qp[t];
        __syncthreads();
        for (int q = 0; q < 64; q++) {
            const float4* qrow = (const float4*)&sq[q][0];
            float acc = 0.f;
#pragma unroll
            for (int i = 0; i < 16; i++) {
                float4 v = qrow[i];
                acc += fabsf(kreg[i*4+0] - v.x);   // ascending-d order (matches ref scan)
                acc += fabsf(kreg[i*4+1] - v.y);
                acc += fabsf(kreg[i*4+2] - v.z);
                acc += fabsf(kreg[i*4+3] - v.w);
            }
            best = fminf(best, acc);
        }
    }
    mind[(size_t)bh * LC + key] = best;
}

// ------------- exact 512 smallest per bh: radix select + ordered tie fill ----
__global__ void topk_kernel(const float* __restrict__ mind, int* __restrict__ idxout) {
    int bh = blockIdx.x, tid = threadIdx.x;   // 256 threads, 16 keys each
    const float* mp = mind + (size_t)bh * LC;
    __shared__ unsigned int hist[256];
    __shared__ unsigned int s_pref;
    __shared__ int s_rem;
    __shared__ int s_cnt;
    __shared__ int s_scan[257];
    unsigned int keys[16];
#pragma unroll
    for (int i = 0; i < 16; i++) keys[i] = __float_as_uint(mp[tid * 16 + i]);
    if (tid == 0) { s_pref = 0u; s_rem = TK; s_cnt = 0; }
    __syncthreads();

    for (int shift = 24; shift >= 0; shift -= 8) {
        hist[tid] = 0u;
        __syncthreads();
        unsigned int pref = s_pref;
#pragma unroll
        for (int i = 0; i < 16; i++) {
            unsigned int k = keys[i];
            bool match = (shift == 24) ? true : ((k >> (shift + 8)) == (pref >> (shift + 8)));
            if (match) atomicAdd(&hist[(k >> shift) & 255u], 1u);
        }
        __syncthreads();
        if (tid == 0) {
            unsigned int cum = 0; int rem = s_rem;
            for (int d = 0; d < 256; d++) {
                unsigned int h = hist[d];
                if (cum + h >= (unsigned int)rem) {
                    s_pref = pref | ((unsigned int)d << shift);
                    s_rem = rem - (int)cum;
                    break;
                }
                cum += h;
            }
        }
        __syncthreads();
    }
    unsigned int T = s_pref;
    int rem = s_rem;

#pragma unroll
    for (int i = 0; i < 16; i++) {
        if (keys[i] < T) {
            int pos = atomicAdd(&s_cnt, 1);
            idxout[(size_t)bh * TK + pos] = tid * 16 + i;
        }
    }
    __syncthreads();
    int base = s_cnt;

    int ceq = 0;
#pragma unroll
    for (int i = 0; i < 16; i++) if (keys[i] == T) ceq++;
    s_scan[tid + 1] = ceq;
    if (tid == 0) s_scan[0] = 0;
    __syncthreads();
    if (tid == 0) for (int i = 1; i <= 256; i++) s_scan[i] += s_scan[i - 1];
    __syncthreads();
    int off = s_scan[tid], r = 0;
#pragma unroll
    for (int i = 0; i < 16; i++) {
        if (keys[i] == T) {
            if (off + r < rem) idxout[(size_t)bh * TK + base + off + r] = tid * 16 + i;
            r++;
        }
    }
}

// ---------------- gather selected K/V rows ----------------
__global__ void gather_kernel(const float* __restrict__ K, const float* __restrict__ V,
                              const int* __restrict__ idx,
                              float* __restrict__ Ks, float* __restrict__ Vs) {
    int bh = blockIdx.y;
    int t = blockIdx.x * 4 + (threadIdx.x >> 6);
    int d = threadIdx.x & 63;
    int src = idx[(size_t)bh * TK + t];
    Ks[((size_t)bh * TK + t) * DH + d] = K[((size_t)bh * LC + src) * DH + d];
    Vs[((size_t)bh * TK + t) * DH + d] = V[((size_t)bh * LC + src) * DH + d];
}

// -------- attention: one thread = one query, 32-key smem chunks --------------
__global__ __launch_bounds__(128) void attn_kernel(const float* __restrict__ Qn,
                                                   const float* __restrict__ Ksel,
                                                   const float* __restrict__ Vsel,
                                                   float* __restrict__ aout) {
    __shared__ __align__(16) float Ks[32][64];
    __shared__ __align__(16) float Vs[32][64];
    int bh = blockIdx.y;
    int b = bh / HH, h = bh % HH;
    int lq = blockIdx.x * 128 + threadIdx.x;
    int tid = threadIdx.x;

    float q[64], o[64];
    const float4* qp = (const float4*)(Qn + ((size_t)bh * LQ + lq) * DH);
#pragma unroll
    for (int i = 0; i < 16; i++) {
        float4 v = qp[i];
        q[i*4+0]=v.x; q[i*4+1]=v.y; q[i*4+2]=v.z; q[i*4+3]=v.w;
    }
#pragma unroll
    for (int d = 0; d < 64; d++) o[d] = 0.f;
    float m = -FLT_MAX, l = 0.f;

    for (int c = 0; c < TK / 32; c++) {
        __syncthreads();
        const float4* kp = (const float4*)(Ksel + ((size_t)bh * TK + c * 32) * DH);
        const float4* vp = (const float4*)(Vsel + ((size_t)bh * TK + c * 32) * DH);
        for (int t = tid; t < 512; t += 128) {
            ((float4*)&Ks[0][0])[t] = kp[t];
            ((float4*)&Vs[0][0])[t] = vp[t];
        }
        __syncthreads();
        float s[32];
        float cmax = -FLT_MAX;
#pragma unroll
        for (int kk = 0; kk < 32; kk++) {
            const float4* kr = (const float4*)&Ks[kk][0];
            float acc = 0.f;
#pragma unroll
            for (int i = 0; i < 16; i++) {
                float4 v = kr[i];
                acc += q[i*4+0]*v.x + q[i*4+1]*v.y + q[i*4+2]*v.z + q[i*4+3]*v.w;
            }
            s[kk] = acc;
            cmax = fmaxf(cmax, acc);
        }
        float mnew = fmaxf(m, cmax);
        float corr = __expf(m - mnew);
        m = mnew;
        l *= corr;
#pragma unroll
        for (int d = 0; d < 64; d++) o[d] *= corr;
#pragma unroll
        for (int kk = 0; kk < 32; kk++) {
            float p = __expf(s[kk] - m);
            l += p;
            const float4* vr = (const float4*)&Vs[kk][0];
#pragma unroll
            for (int i = 0; i < 16; i++) {
                float4 v = vr[i];
                o[i*4+0] += p * v.x; o[i*4+1] += p * v.y;
                o[i*4+2] += p * v.z; o[i*4+3] += p * v.w;
            }
        }
    }
    float invl = 1.0f / l;
#pragma unroll
    for (int d = 0; d < 64; d++)
        aout[((size_t)(b * CC) + h * 64 + d) * LQ + lq] = o[d] * invl;
}

// ---------------- launch ----------------
extern "C" void kernel_launch(void* const* d_in, const int* in_sizes, int n_in,
                              void* d_out, int out_size) {
    const float* query_source = (const float*)d_in[0];
    const float* context      = (const float*)d_in[1];
    const float* cn_g = (const float*)d_in[2];
    const float* cn_b = (const float*)d_in[3];
    const float* qn_g = (const float*)d_in[4];
    const float* qn_b = (const float*)d_in[5];
    const float* on_g = (const float*)d_in[6];
    const float* on_b = (const float*)d_in[7];
    const float* w_kv = (const float*)d_in[8];
    const float* w_q  = (const float*)d_in[9];
    const float* w_out= (const float*)d_in[10];
    const float* gamma= (const float*)d_in[11];
    float* out = (float*)d_out;

    float *ctxn, *qsn, *kv, *qprj, *K, *V, *Qn, *Qs, *mind, *Ksel, *Vsel, *aout, *oprj;
    int* idx;
    cudaGetSymbolAddress((void**)&ctxn, g_ctxn);
    cudaGetSymbolAddress((void**)&qsn,  g_qsn);
    cudaGetSymbolAddress((void**)&kv,   g_kv);
    cudaGetSymbolAddress((void**)&qprj, g_qprj);
    cudaGetSymbolAddress((void**)&K,    g_K);
    cudaGetSymbolAddress((void**)&V,    g_V);
    cudaGetSymbolAddress((void**)&Qn,   g_Qn);
    cudaGetSymbolAddress((void**)&Qs,   g_Qs);
    cudaGetSymbolAddress((void**)&mind, g_mind);
    cudaGetSymbolAddress((void**)&idx,  g_idx);
    cudaGetSymbolAddress((void**)&Ksel, g_Ksel);
    cudaGetSymbolAddress((void**)&Vsel, g_Vsel);
    cudaGetSymbolAddress((void**)&aout, g_aout);
    cudaGetSymbolAddress((void**)&oprj, g_oprj);

    // 1. channel LN
    ln_kernel<<<dim3(LC/128, BB), 128>>>(context, cn_g, cn_b, ctxn, CC, LC);
    ln_kernel<<<dim3(LQ/128, BB), 128>>>(query_source, qn_g, qn_b, qsn, CC, LQ);

    // 2. projections
    sgemm128<<<dim3(LC/128, 1024/128, BB), 256>>>(w_kv, ctxn, kv, CC, LC,
                                                  (size_t)CC*LC, (size_t)2*CC*LC);
    sgemm128<<<dim3(LQ/128, CC/128, BB), 256>>>(w_q, qsn, qprj, CC, LQ,
                                                (size_t)CC*LQ, (size_t)CC*LQ);

    // 3. fold heads + norm + transpose
    nt_kernel<<<dim3(LC/32, HH, BB), 256>>>(kv, K, LC, 2*CC, 0,   1);
    nt_kernel<<<dim3(LC/32, HH, BB), 256>>>(kv, V, LC, 2*CC, CC,  0);
    nt_kernel<<<dim3(LQ/32, HH, BB), 256>>>(qprj, Qn, LQ, CC, 0,  1);

    // 4. random query subset
    qsmall_kernel<<<dim3(TK, BHD), 64>>>(Qn, Qs);

    // 5. min-L1 distance
    dist_kernel<<<dim3(LC/256, BHD), 256>>>(K, Qs, mind);

    // 6. exact top-512 smallest
    topk_kernel<<<BHD, 256>>>(mind, idx);

    // 7. gather
    gather_kernel<<<dim3(TK/4, BHD), 256>>>(K, V, idx, Ksel, Vsel);

    // 8. attention
    attn_kernel<<<dim3(LQ/128, BHD), 128>>>(Qn, Ksel, Vsel, aout);

    // 9. output projection
    sgemm128<<<dim3(LQ/128, CC/128, BB), 256>>>(w_out, aout, oprj, CC, LQ,
                                                (size_t)CC*LQ, (size_t)CC*LQ);

    // 10. final LN + residual
    ln_resid_kernel<<<dim3(LQ/128, BB), 128>>>(oprj, on_g, on_b, query_source,
                                               gamma, out, CC, LQ);
}